// round 13
// baseline (speedup 1.0000x reference)
#include <cuda_runtime.h>
#include <cstdint>

// HairBundle SDE drift + constant diffusion. Streaming, memory-bound.
// Floor: 480MB (160R+320W) -> ~60us @ 8TB/s.
// R10 (best, 74.1 total / 67.2 kernel / DRAM 78.8%): cp.async reads +
// cp.async.bulk S2G stores (2560B bursts), issue 24%, occ 90%.
// R11: R10 + 2-tile per-warp double buffer (R8's proven shape): both tiles'
// reads in flight up front; t1 compute overlaps t0's bulk-store drain; one
// final bulk wait per warp. smem 42.5KB -> 5 blocks/SM.

#define TPB 256
#define WPB (TPB / 32)
#define F4T 160                      // float4 per warp-tile = 128 rows
#define TILE_BYTES (F4T * 16)        // 2560
#define ROWS_PER_WARP 256            // 2 tiles

__device__ __forceinline__ void hb_row(float x_hb, float x_a, float p_m,
                                       float p_gs, float p_t, float force,
                                       float* __restrict__ o) {
    float z    = 4.0f * (x_hb - x_a);                 // (x_hb - x_a)/DELTA
    float p_o  = 1.0f / (1.0f + __expf(-z));          // sigmoid
    float f_gs = 0.75f * (x_hb - x_a - 0.5f * p_o);
    o[0] = -f_gs - 0.6f * x_hb + force;
    o[1] = 0.1f * (f_gs - 0.45f * x_a - 0.35f * (1.0f - 0.9f * p_m));
    o[2] = 1.2f * p_o * (1.0f - p_m)  - 0.8f * p_m;
    o[3] = 0.7f * p_o * (1.0f - p_gs) - 0.5f * p_gs;
    o[4] = 0.3f * p_o * (1.0f - p_t)  - 0.4f * p_t;
}

__device__ __forceinline__ void cp_async16(uint32_t smem_addr, const void* gptr) {
    asm volatile("cp.async.cg.shared.global [%0], [%1], 16;\n"
                 :: "r"(smem_addr), "l"(gptr));
}

__device__ __forceinline__ void bulk_s2g(void* gptr, uint32_t smem_addr,
                                         uint32_t bytes) {
    asm volatile("cp.async.bulk.global.shared::cta.bulk_group [%0], [%1], %2;\n"
                 :: "l"(gptr), "r"(smem_addr), "r"(bytes) : "memory");
}

__device__ __forceinline__ void issue_reads(uint32_t sslot,
                                            const float4* __restrict__ g,
                                            int lane) {
    #pragma unroll
    for (int k = 0; k < 5; k++)
        cp_async16(sslot + (uint32_t)(lane + k * 32) * 16u, g + lane + k * 32);
    asm volatile("cp.async.commit_group;\n" ::: "memory");
}

// compute 4 rows in place in a warp-private 160-f4 slab (lane slice i5=lane*5)
__device__ __forceinline__ void compute_tile(float4* __restrict__ sb, int lane,
                                             float force) {
    const int i5 = lane * 5;
    float4 a = sb[i5 + 0];
    float4 b = sb[i5 + 1];
    float o0[5], o1[5];
    hb_row(a.x, a.y, a.z, a.w, b.x, force, o0);       // row 0
    float4 c = sb[i5 + 2];
    hb_row(b.y, b.z, b.w, c.x, c.y, force, o1);       // row 1
    sb[i5 + 0] = make_float4(o0[0], o0[1], o0[2], o0[3]);
    sb[i5 + 1] = make_float4(o0[4], o1[0], o1[1], o1[2]);
    float4 d = sb[i5 + 3];
    float o2[5];
    hb_row(c.z, c.w, d.x, d.y, d.z, force, o2);       // row 2
    sb[i5 + 2] = make_float4(o1[3], o1[4], o2[0], o2[1]);
    float4 e = sb[i5 + 4];
    float o3[5];
    hb_row(d.w, e.x, e.y, e.z, e.w, force, o3);       // row 3
    sb[i5 + 3] = make_float4(o2[2], o2[3], o2[4], o3[0]);
    sb[i5 + 4] = make_float4(o3[1], o3[2], o3[3], o3[4]);
}

__global__ __launch_bounds__(TPB, 5)
void hb_kernel(const float* __restrict__ t,
               const float4* __restrict__ x4,
               float4* __restrict__ drift4,
               float4* __restrict__ diffu4,
               int nf4, int B) {
    __shared__ float4 buf[WPB][2][F4T];  // 40KB: two slabs per warp
    __shared__ float4 slab[F4T];         // 2.5KB: constant diffusion tile
    const int tid  = threadIdx.x;
    const int lane = tid & 31;
    const int w    = tid >> 5;
    const int wid  = blockIdx.x * WPB + w;            // global warp id
    const int base = wid * (2 * F4T);                  // f4 offset of tile pair
    const int row_base = wid * ROWS_PER_WARP;

    int nfull = 0;
    if (row_base + 128 <= B) nfull = 1;
    if (row_base + 256 <= B) nfull = 2;

    uint32_t s0 = (uint32_t)__cvta_generic_to_shared(&buf[w][0][0]);
    uint32_t s1 = (uint32_t)__cvta_generic_to_shared(&buf[w][1][0]);

    // ---- issue reads for all my full tiles up front ----
    if (nfull >= 1) issue_reads(s0, x4 + base, lane);
    if (nfull == 2) issue_reads(s1, x4 + base + F4T, lane);

    // ---- diffusion slab: period-5 f4 pattern; every tile base % 5 == 0 ----
    if (tid < F4T) {
        int p = tid % 5;
        slab[tid] = (p == 0) ? make_float4(0.05f, 0.02f, 0.0f,  0.0f)  :
                    (p == 1) ? make_float4(0.0f,  0.05f, 0.02f, 0.0f)  :
                    (p == 2) ? make_float4(0.0f,  0.0f,  0.05f, 0.02f) :
                    (p == 3) ? make_float4(0.0f,  0.0f,  0.0f,  0.05f) :
                               make_float4(0.02f, 0.0f,  0.0f,  0.0f);
    }
    __syncthreads();   // all threads reach this; slab visible block-wide

    const float force = 0.5f * __sinf(6.283185307179586f * t[0]);
    uint32_t sslab = (uint32_t)__cvta_generic_to_shared(&slab[0]);

    if (nfull == 2) {
        // ---- tile 0: wait oldest group only; t1 reads keep streaming ----
        asm volatile("cp.async.wait_group 1;\n" ::: "memory");
        __syncwarp();
        compute_tile(&buf[w][0][0], lane, force);
        __syncwarp();
        if (lane == 0) {
            asm volatile("fence.proxy.async.shared::cta;\n" ::: "memory");
            bulk_s2g(drift4 + base, s0, TILE_BYTES);
            bulk_s2g(diffu4 + base, sslab, TILE_BYTES);
            asm volatile("cp.async.bulk.commit_group;\n" ::: "memory");
        }
        // ---- tile 1: compute overlaps tile 0's store drain ----
        asm volatile("cp.async.wait_group 0;\n" ::: "memory");
        __syncwarp();
        compute_tile(&buf[w][1][0], lane, force);
        __syncwarp();
        if (lane == 0) {
            asm volatile("fence.proxy.async.shared::cta;\n" ::: "memory");
            bulk_s2g(drift4 + base + F4T, s1, TILE_BYTES);
            bulk_s2g(diffu4 + base + F4T, sslab, TILE_BYTES);
            asm volatile("cp.async.bulk.commit_group;\n" ::: "memory");
            asm volatile("cp.async.bulk.wait_group 0;\n" ::: "memory");
        }
    } else if (nfull == 1) {
        asm volatile("cp.async.wait_group 0;\n" ::: "memory");
        __syncwarp();
        compute_tile(&buf[w][0][0], lane, force);
        __syncwarp();
        if (lane == 0) {
            asm volatile("fence.proxy.async.shared::cta;\n" ::: "memory");
            bulk_s2g(drift4 + base, s0, TILE_BYTES);
            bulk_s2g(diffu4 + base, sslab, TILE_BYTES);
            asm volatile("cp.async.bulk.commit_group;\n" ::: "memory");
            asm volatile("cp.async.bulk.wait_group 0;\n" ::: "memory");
        }
    }

    // ---- scalar remainder rows in my range (empty for B=8M) ----
    int r0 = row_base + nfull * 128;
    int r1 = row_base + ROWS_PER_WARP; if (r1 > B) r1 = B;
    if (r0 < r1) {
        const float* xs = (const float*)x4;
        float* drs = (float*)drift4;
        float* dfs = (float*)diffu4;
        for (int r = r0 + lane; r < r1; r += 32) {
            const float* xr = xs + (size_t)r * 5;
            float o[5];
            hb_row(xr[0], xr[1], xr[2], xr[3], xr[4], force, o);
            float* dr = drs + (size_t)r * 5;
            float* gr = dfs + (size_t)r * 5;
            dr[0] = o[0]; dr[1] = o[1]; dr[2] = o[2]; dr[3] = o[3]; dr[4] = o[4];
            gr[0] = 0.05f; gr[1] = 0.02f; gr[2] = 0.0f; gr[3] = 0.0f; gr[4] = 0.0f;
        }
    }
}

extern "C" void kernel_launch(void* const* d_in, const int* in_sizes, int n_in,
                              void* d_out, int out_size) {
    const float* t  = (const float*)d_in[0];   // [1]
    const float* x  = (const float*)d_in[1];   // [B*5]
    float* out      = (float*)d_out;
    int B           = in_sizes[1] / 5;
    int nf4         = in_sizes[1] / 4;         // B*5 % 4 == 0 for B=8M
    float* drift    = out;
    float* diffu    = out + (size_t)out_size / 2;

    int nwarps  = (B + ROWS_PER_WARP - 1) / ROWS_PER_WARP;  // 31250 for B=8M
    int nblocks = (nwarps + WPB - 1) / WPB;                 // 3907

    hb_kernel<<<nblocks, TPB>>>(t, (const float4*)x,
                                (float4*)drift, (float4*)diffu, nf4, B);
}

// round 15
// speedup vs baseline: 1.0039x; 1.0039x over previous
#include <cuda_runtime.h>
#include <cstdint>

// HairBundle SDE drift + constant diffusion. Streaming, memory-bound.
// Floor: 480MB (160R+320W) -> ~60us @ 8TB/s.
// R10 (best, 74.08 total / 67.2 kernel / DRAM 78.8% / occ 90%): cp.async
// reads + cp.async.bulk S2G stores. R11 (2-tile, occ 57%) slightly worse --
// occupancy beats intra-warp overlap, again.
// R12 = R10 + diffusion bulk-store issued BEFORE the read wait: each warp's
// 2560B write burst is in flight during its DRAM-read stall window, so reads
// and writes interleave instead of phase-alternating.

#define TPB 256
#define WPB (TPB / 32)
#define F4T 160                      // float4 per warp-tile = 128 rows
#define TILE_BYTES (F4T * 16)        // 2560

__device__ __forceinline__ void hb_row(float x_hb, float x_a, float p_m,
                                       float p_gs, float p_t, float force,
                                       float* __restrict__ o) {
    float z    = 4.0f * (x_hb - x_a);                 // (x_hb - x_a)/DELTA
    float p_o  = 1.0f / (1.0f + __expf(-z));          // sigmoid
    float f_gs = 0.75f * (x_hb - x_a - 0.5f * p_o);
    o[0] = -f_gs - 0.6f * x_hb + force;
    o[1] = 0.1f * (f_gs - 0.45f * x_a - 0.35f * (1.0f - 0.9f * p_m));
    o[2] = 1.2f * p_o * (1.0f - p_m)  - 0.8f * p_m;
    o[3] = 0.7f * p_o * (1.0f - p_gs) - 0.5f * p_gs;
    o[4] = 0.3f * p_o * (1.0f - p_t)  - 0.4f * p_t;
}

__device__ __forceinline__ void cp_async16(uint32_t smem_addr, const void* gptr) {
    asm volatile("cp.async.cg.shared.global [%0], [%1], 16;\n"
                 :: "r"(smem_addr), "l"(gptr));
}

__device__ __forceinline__ void bulk_s2g(void* gptr, uint32_t smem_addr,
                                         uint32_t bytes) {
    asm volatile("cp.async.bulk.global.shared::cta.bulk_group [%0], [%1], %2;\n"
                 :: "l"(gptr), "r"(smem_addr), "r"(bytes) : "memory");
}

__global__ __launch_bounds__(TPB, 8)
void hb_kernel(const float* __restrict__ t,
               const float4* __restrict__ x4,
               float4* __restrict__ drift4,
               float4* __restrict__ diffu4,
               int nf4, int B) {
    __shared__ float4 buf[WPB][F4T];     // 20KB: in-place input->drift slabs
    __shared__ float4 slab[F4T];         // 2.5KB: constant diffusion tile
    const int tid  = threadIdx.x;
    const int lane = tid & 31;
    const int w    = tid >> 5;
    const int wid  = blockIdx.x * WPB + w;            // global warp id
    const int base = wid * F4T;                        // f4 offset (fits int)
    const bool full = (base + F4T <= nf4);

    // ---- issue this warp's reads first (overlaps slab fill + barrier) ----
    uint32_t sbase = (uint32_t)__cvta_generic_to_shared(&buf[w][0]);
    if (full) {
        #pragma unroll
        for (int k = 0; k < 5; k++)
            cp_async16(sbase + (uint32_t)(lane + k * 32) * 16u,
                       x4 + base + lane + k * 32);
        asm volatile("cp.async.commit_group;\n" ::: "memory");
    }

    // ---- diffusion slab: period-5 f4 pattern; every tile base % 5 == 0 ----
    if (tid < F4T) {
        int p = tid % 5;
        slab[tid] = (p == 0) ? make_float4(0.05f, 0.02f, 0.0f,  0.0f)  :
                    (p == 1) ? make_float4(0.0f,  0.05f, 0.02f, 0.0f)  :
                    (p == 2) ? make_float4(0.0f,  0.0f,  0.05f, 0.02f) :
                    (p == 3) ? make_float4(0.0f,  0.0f,  0.0f,  0.05f) :
                               make_float4(0.02f, 0.0f,  0.0f,  0.0f);
    }
    __syncthreads();   // all threads reach this; slab visible block-wide

    const float force = 0.5f * __sinf(6.283185307179586f * t[0]);

    if (full) {
        // ---- diffusion bulk-store NOW: write burst in flight during the
        //      read wait below (diffusion depends only on the slab) ----
        if (lane == 0) {
            asm volatile("fence.proxy.async.shared::cta;\n" ::: "memory");
            uint32_t sslab = (uint32_t)__cvta_generic_to_shared(&slab[0]);
            bulk_s2g(diffu4 + base, sslab, TILE_BYTES);
            asm volatile("cp.async.bulk.commit_group;\n" ::: "memory");
        }

        asm volatile("cp.async.wait_group 0;\n" ::: "memory");
        __syncwarp();

        // compute 4 rows in place (lane slice i5 = lane*5)
        {
            const int i5 = lane * 5;
            float4 a = buf[w][i5 + 0];
            float4 b = buf[w][i5 + 1];
            float o0[5], o1[5];
            hb_row(a.x, a.y, a.z, a.w, b.x, force, o0);       // row 0
            float4 c = buf[w][i5 + 2];
            hb_row(b.y, b.z, b.w, c.x, c.y, force, o1);       // row 1
            buf[w][i5 + 0] = make_float4(o0[0], o0[1], o0[2], o0[3]);
            buf[w][i5 + 1] = make_float4(o0[4], o1[0], o1[1], o1[2]);
            float4 d = buf[w][i5 + 3];
            float o2[5];
            hb_row(c.z, c.w, d.x, d.y, d.z, force, o2);       // row 2
            buf[w][i5 + 2] = make_float4(o1[3], o1[4], o2[0], o2[1]);
            float4 e = buf[w][i5 + 4];
            float o3[5];
            hb_row(d.w, e.x, e.y, e.z, e.w, force, o3);       // row 3
            buf[w][i5 + 3] = make_float4(o2[2], o2[3], o2[4], o3[0]);
            buf[w][i5 + 4] = make_float4(o3[1], o3[2], o3[3], o3[4]);
        }
        __syncwarp();   // all lanes' smem writes done before bulk issue

        if (lane == 0) {
            asm volatile("fence.proxy.async.shared::cta;\n" ::: "memory");
            bulk_s2g(drift4 + base, sbase, TILE_BYTES);
            asm volatile("cp.async.bulk.commit_group;\n" ::: "memory");
            asm volatile("cp.async.bulk.wait_group 0;\n" ::: "memory");
        }
    } else {
        // ---- partial warp: scalar per-row fallback (empty for B=8M) ----
        const float* xs = (const float*)x4;
        float* drs = (float*)drift4;
        float* dfs = (float*)diffu4;
        int row0 = wid * 128;                 // 160 f4 = 128 rows per warp
        for (int r = row0 + lane; r < B; r += 32) {
            const float* xr = xs + (size_t)r * 5;
            float o[5];
            hb_row(xr[0], xr[1], xr[2], xr[3], xr[4], force, o);
            float* dr = drs + (size_t)r * 5;
            float* gr = dfs + (size_t)r * 5;
            dr[0] = o[0]; dr[1] = o[1]; dr[2] = o[2]; dr[3] = o[3]; dr[4] = o[4];
            gr[0] = 0.05f; gr[1] = 0.02f; gr[2] = 0.0f; gr[3] = 0.0f; gr[4] = 0.0f;
        }
    }
}

extern "C" void kernel_launch(void* const* d_in, const int* in_sizes, int n_in,
                              void* d_out, int out_size) {
    const float* t  = (const float*)d_in[0];   // [1]
    const float* x  = (const float*)d_in[1];   // [B*5]
    float* out      = (float*)d_out;
    int B           = in_sizes[1] / 5;
    int nf4         = in_sizes[1] / 4;         // B*5 % 4 == 0 for B=8M
    float* drift    = out;
    float* diffu    = out + (size_t)out_size / 2;

    int nwarps  = (B + 127) / 128;             // 62500 for B=8M
    int nblocks = (nwarps + WPB - 1) / WPB;    // 7813

    hb_kernel<<<nblocks, TPB>>>(t, (const float4*)x,
                                (float4*)drift, (float4*)diffu, nf4, B);
}